// round 5
// baseline (speedup 1.0000x reference)
#include <cuda_runtime.h>
#include <cuda_bf16.h>
#include <stdint.h>
#include <math.h>

#define BB 16
#define TT 2048
#define DD 256

// Certification threshold: computed (bf16-mma) lower bound on a row/col max.
// tanh saturates to exactly 1.0f for x >= ~9.0; bf16 pipeline error << 0.6,
// so a computed bound >= 9.6 certifies saturation of that row/col max.
#define CERT_THRESH 9.6f

// ---------------- scratch (static __device__ arrays; no runtime allocation) ----
__device__ __nv_bfloat16 g_qb[BB*TT*DD];    // q in bf16
__device__ __nv_bfloat16 g_ab[BB*TT*DD];    // a in bf16
__device__ __nv_bfloat16 g_Ut[DD*DD];       // U^T in bf16
__device__ __nv_bfloat16 g_qU[BB*TT*DD];    // qU in bf16
__device__ unsigned      g_rmax[BB*TT];     // encoded float max per q-row
__device__ unsigned      g_cmax[BB*TT];     // encoded float max per a-col
__device__ float         g_wts[2*BB*TT];    // softmax weights (fallback)
__device__ float         g_part[2*BB*8*DD]; // pooling partials (fallback)
__device__ float         g_meanpart[512*4*DD]; // per-(chunk,rowgroup) mean partials
__device__ int           g_need_full;       // 0 = certified (means exact)

// ---------------- helpers ----------------
__device__ __forceinline__ uint32_t smem_u32(const void* p) {
    uint32_t r;
    asm("{ .reg .u64 t; cvta.to.shared.u64 t, %1; cvt.u32.u64 %0, t; }"
        : "=r"(r) : "l"(p));
    return r;
}

__device__ __forceinline__ void cpasync16(uint32_t s, const void* g) {
    asm volatile("cp.async.cg.shared.global [%0], [%1], 16;" :: "r"(s), "l"(g) : "memory");
}
#define CP_COMMIT() asm volatile("cp.async.commit_group;" ::: "memory")
#define CP_WAIT0()  asm volatile("cp.async.wait_group 0;" ::: "memory")

__device__ __forceinline__ void ldmx4(uint32_t addr, uint32_t& r0, uint32_t& r1,
                                      uint32_t& r2, uint32_t& r3) {
    asm volatile("ldmatrix.sync.aligned.m8n8.x4.shared.b16 {%0,%1,%2,%3}, [%4];"
                 : "=r"(r0), "=r"(r1), "=r"(r2), "=r"(r3) : "r"(addr));
}

__device__ __forceinline__ void mma16816(float* c, uint32_t a0, uint32_t a1,
                                         uint32_t a2, uint32_t a3,
                                         uint32_t b0, uint32_t b1) {
    asm volatile(
        "mma.sync.aligned.m16n8k16.row.col.f32.bf16.bf16.f32 "
        "{%0,%1,%2,%3}, {%4,%5,%6,%7}, {%8,%9}, {%0,%1,%2,%3};"
        : "+f"(c[0]), "+f"(c[1]), "+f"(c[2]), "+f"(c[3])
        : "r"(a0), "r"(a1), "r"(a2), "r"(a3), "r"(b0), "r"(b1));
}

// order-preserving float <-> unsigned encoding (atomicMax(unsigned) == float max)
__device__ __forceinline__ unsigned encf(float f) {
    unsigned u = __float_as_uint(f);
    return (u & 0x80000000u) ? ~u : (u | 0x80000000u);
}
__device__ __forceinline__ float decf(unsigned e) {
    unsigned u = (e & 0x80000000u) ? (e & 0x7FFFFFFFu) : ~e;
    return __uint_as_float(u);
}

// ---------------- GEMM core: C[128x128] = A[128x256] * B[128x256]^T -----------
#define GEMM_SMEM 65536

__device__ __forceinline__ void load_chunk(uint32_t smb, int buf,
                                           const __nv_bfloat16* __restrict__ A,
                                           const __nv_bfloat16* __restrict__ Bm,
                                           int ck, int tid) {
    const __nv_bfloat16* Ac = A + ck * 64;
    const __nv_bfloat16* Bc = Bm + ck * 64;
    #pragma unroll
    for (int i = 0; i < 4; i++) {
        int v = tid + i * 256;
        int row = v >> 3, kv = v & 7;
        uint32_t o = (uint32_t)row * 128u + (uint32_t)kv * 16u;
        o ^= (o >> 3) & 0x70u;
        const size_t goff = (size_t)row * DD + (size_t)kv * 8;
        cpasync16(smb + buf * 16384 + o, Ac + goff);
        cpasync16(smb + 32768 + buf * 16384 + o, Bc + goff);
    }
}

// Single-sync double-buffered pipeline:
//   wait(chunk ck) -> syncthreads -> prefetch ck+1 -> compute ck
__device__ __forceinline__ void gemm_mainloop(uint32_t smb, const __nv_bfloat16* A,
                                              const __nv_bfloat16* Bm, int tid,
                                              float acc[4][4][4]) {
    const int lid = tid & 31, w = tid >> 5;
    const int wm = (w >> 2) * 64, wn = (w & 3) * 32;
    const int lrow = lid & 15;
    const uint32_t khalf = (uint32_t)(lid >> 4) * 16u;

    load_chunk(smb, 0, A, Bm, 0, tid);
    CP_COMMIT();

    #pragma unroll
    for (int ck = 0; ck < 4; ck++) {
        CP_WAIT0();
        __syncthreads();
        if (ck + 1 < 4) {
            load_chunk(smb, (ck + 1) & 1, A, Bm, ck + 1, tid);
            CP_COMMIT();
        }

        const uint32_t abase = smb + (ck & 1) * 16384;
        const uint32_t bbase = smb + 32768 + (ck & 1) * 16384;

        #pragma unroll
        for (int kk = 0; kk < 4; kk++) {
            const uint32_t koff = (uint32_t)kk * 32u + khalf;
            uint32_t a[4][4];
            #pragma unroll
            for (int mt = 0; mt < 4; mt++) {
                uint32_t o = (uint32_t)(wm + mt * 16 + lrow) * 128u + koff;
                o ^= (o >> 3) & 0x70u;
                ldmx4(abase + o, a[mt][0], a[mt][1], a[mt][2], a[mt][3]);
            }
            uint32_t b[4][2];
            #pragma unroll
            for (int np = 0; np < 2; np++) {
                uint32_t o = (uint32_t)(wn + np * 16 + lrow) * 128u + koff;
                o ^= (o >> 3) & 0x70u;
                uint32_t r0, r1, r2, r3;
                ldmx4(bbase + o, r0, r1, r2, r3);
                b[np * 2 + 0][0] = r0; b[np * 2 + 0][1] = r2;
                b[np * 2 + 1][0] = r1; b[np * 2 + 1][1] = r3;
            }
            #pragma unroll
            for (int mt = 0; mt < 4; mt++)
                #pragma unroll
                for (int nt = 0; nt < 4; nt++)
                    mma16816(acc[mt][nt], a[mt][0], a[mt][1], a[mt][2], a[mt][3],
                             b[nt][0], b[nt][1]);
        }
    }
}

// ---------------- k0: convert fp32->bf16 + mean partials (+ optional aux) -----
// Convert blocks: bx < 256. meanpart slot = slotbase + bx. Aux blocks (do_aux):
// bx in [256, 324): 64 zero blocks + 4 U-transpose blocks.
__global__ void __launch_bounds__(256) k0_convert(const float* __restrict__ src0,
                                                  const float* __restrict__ U,
                                                  __nv_bfloat16* __restrict__ dst0,
                                                  int slotbase, int do_aux) {
    int bx = blockIdx.x;
    int tid = threadIdx.x;

    if (bx >= 256) {
        if (!do_aux) return;
        int bz = bx - 256;
        if (bz < 64) {
            int i0 = (bz * 256 + tid) * 2;
            g_rmax[i0] = 0u; g_rmax[i0 + 1] = 0u;
            g_cmax[i0] = 0u; g_cmax[i0 + 1] = 0u;
            if (bz == 0 && tid == 0) g_need_full = 0;
        } else {
            int blk = bz - 64;   // 0..3
            #pragma unroll 4
            for (int it = 0; it < 64; it++) {
                int i = blk * 16384 + it * 256 + tid;
                int d = i >> 8, e = i & 255;
                g_Ut[e * DD + d] = __float2bfloat16(U[i]);
            }
        }
        return;
    }

    int b = bx >> 4;
    int chunk = bx & 15;
    const float4* src = (const float4*)(src0 + ((size_t)b * TT + (size_t)chunk * 128) * DD);
    uint2* dst = (uint2*)(dst0 + ((size_t)b * TT + (size_t)chunk * 128) * DD);

    const int dvec = tid & 63;          // float4 index within row
    const int rg = tid >> 6;            // row group 0..3
    float4 s = make_float4(0.f, 0.f, 0.f, 0.f);
    #pragma unroll 4
    for (int it = 0; it < 32; it++) {
        int row = it * 4 + rg;
        float4 v = src[(size_t)row * 64 + dvec];
        s.x += v.x; s.y += v.y; s.z += v.z; s.w += v.w;
        __nv_bfloat162 lo = __floats2bfloat162_rn(v.x, v.y);
        __nv_bfloat162 hi = __floats2bfloat162_rn(v.z, v.w);
        uint2 o;
        o.x = *reinterpret_cast<unsigned*>(&lo);
        o.y = *reinterpret_cast<unsigned*>(&hi);
        dst[(size_t)row * 64 + dvec] = o;
    }
    float4* mp = (float4*)&g_meanpart[((size_t)(slotbase + bx) * 4 + rg) * DD];
    mp[dvec] = s;
}

// ---------------- k1: qU = q @ U (via Ut rows), bf16 out ----------------------
// tileM enumerated via a mapping so it can be split: part=0 -> per-batch row
// blocks {0,1} (64 CTAs); part=1 -> row blocks {2..15} (448 CTAs).
__global__ void __launch_bounds__(256, 2) k1_qU(int part) {
    extern __shared__ char sm[];
    uint32_t smb = smem_u32(sm);
    int tid = threadIdx.x;
    int tileN = blockIdx.x;   // 0..1
    int y = blockIdx.y;
    int tileM = part ? ((y / 14) * 16 + 2 + (y % 14))
                     : ((y >> 1) * 16 + (y & 1));

    float acc[4][4][4];
    #pragma unroll
    for (int i = 0; i < 4; i++)
        #pragma unroll
        for (int j = 0; j < 4; j++)
            #pragma unroll
            for (int r = 0; r < 4; r++) acc[i][j][r] = 0.0f;

    const __nv_bfloat16* A = g_qb + (size_t)tileM * 128 * DD;
    const __nv_bfloat16* Bm = g_Ut + (size_t)tileN * 128 * DD;
    gemm_mainloop(smb, A, Bm, tid, acc);

    const int lid = tid & 31, w = tid >> 5;
    const int wm = (w >> 2) * 64, wn = (w & 3) * 32;
    const int g = lid >> 2, tg = lid & 3;
    #pragma unroll
    for (int mt = 0; mt < 4; mt++) {
        int row0 = tileM * 128 + wm + mt * 16 + g;
        #pragma unroll
        for (int nt = 0; nt < 4; nt++) {
            int col = tileN * 128 + wn + nt * 8 + 2 * tg;
            __nv_bfloat162 p0 = __floats2bfloat162_rn(acc[mt][nt][0], acc[mt][nt][1]);
            __nv_bfloat162 p1 = __floats2bfloat162_rn(acc[mt][nt][2], acc[mt][nt][3]);
            *reinterpret_cast<unsigned*>(g_qU + (size_t)row0 * DD + col) =
                *reinterpret_cast<unsigned*>(&p0);
            *reinterpret_cast<unsigned*>(g_qU + (size_t)(row0 + 8) * DD + col) =
                *reinterpret_cast<unsigned*>(&p1);
        }
    }
}

// ---------------- k2: G tile GEMM with fused row/col max ----------------------
__global__ void __launch_bounds__(256, 2) k2_gemm_max(int njoff, int mioff, int gated) {
    if (gated && g_need_full == 0) return;

    extern __shared__ char sm[];
    uint32_t smb = smem_u32(sm);
    int tid = threadIdx.x;
    int nj = blockIdx.x + njoff;
    int mi = blockIdx.y + mioff;
    int b  = blockIdx.z;

    float acc[4][4][4];
    #pragma unroll
    for (int i = 0; i < 4; i++)
        #pragma unroll
        for (int j = 0; j < 4; j++)
            #pragma unroll
            for (int r = 0; r < 4; r++) acc[i][j][r] = 0.0f;

    const __nv_bfloat16* A = g_qU + ((size_t)b * TT + (size_t)mi * 128) * DD;
    const __nv_bfloat16* Bm = g_ab + ((size_t)b * TT + (size_t)nj * 128) * DD;
    gemm_mainloop(smb, A, Bm, tid, acc);

    const int lid = tid & 31, w = tid >> 5;
    const int wm = (w >> 2) * 64, wn = (w & 3) * 32;
    const int g = lid >> 2, tg = lid & 3;
    const int rowBase = b * TT + mi * 128 + wm;
    const int colBase = b * TT + nj * 128 + wn;

    #pragma unroll
    for (int mt = 0; mt < 4; mt++) {
        float r0 = -3.0e38f, r1 = -3.0e38f;
        #pragma unroll
        for (int nt = 0; nt < 4; nt++) {
            r0 = fmaxf(r0, fmaxf(acc[mt][nt][0], acc[mt][nt][1]));
            r1 = fmaxf(r1, fmaxf(acc[mt][nt][2], acc[mt][nt][3]));
        }
        r0 = fmaxf(r0, __shfl_xor_sync(0xffffffffu, r0, 1));
        r0 = fmaxf(r0, __shfl_xor_sync(0xffffffffu, r0, 2));
        r1 = fmaxf(r1, __shfl_xor_sync(0xffffffffu, r1, 1));
        r1 = fmaxf(r1, __shfl_xor_sync(0xffffffffu, r1, 2));
        if (tg == 0) {
            atomicMax(&g_rmax[rowBase + mt * 16 + g], encf(r0));
            atomicMax(&g_rmax[rowBase + mt * 16 + g + 8], encf(r1));
        }
    }
    #pragma unroll
    for (int nt = 0; nt < 4; nt++) {
        float c0 = -3.0e38f, c1 = -3.0e38f;
        #pragma unroll
        for (int mt = 0; mt < 4; mt++) {
            c0 = fmaxf(c0, fmaxf(acc[mt][nt][0], acc[mt][nt][2]));
            c1 = fmaxf(c1, fmaxf(acc[mt][nt][1], acc[mt][nt][3]));
        }
        #pragma unroll
        for (int s = 4; s < 32; s <<= 1) {
            c0 = fmaxf(c0, __shfl_xor_sync(0xffffffffu, c0, s));
            c1 = fmaxf(c1, __shfl_xor_sync(0xffffffffu, c1, s));
        }
        if (g == 0) {
            atomicMax(&g_cmax[colBase + nt * 8 + 2 * tg], encf(c0));
            atomicMax(&g_cmax[colBase + nt * 8 + 2 * tg + 1], encf(c1));
        }
    }
}

// ---------------- k_check: certify saturation of every row/col max ------------
__global__ void k_check() {
    int i = blockIdx.x * 256 + threadIdx.x;   // 0..65535
    unsigned e = (i < BB * TT) ? g_rmax[i] : g_cmax[i - BB * TT];
    if (decf(e) < CERT_THRESH) atomicOr(&g_need_full, 1);
}

// ---------------- k_out: certified path -> means ------------------------------
__global__ void k_out_mean(float* __restrict__ out) {
    if (g_need_full) return;
    int i = blockIdx.x * 256 + threadIdx.x;   // 0..8191
    int which = i >> 12;
    int b = (i >> 8) & 15;
    int d = i & 255;
    size_t base64 = (size_t)(which * 256 + b * 16) * 4;
    float s = 0.0f;
    #pragma unroll 8
    for (int j = 0; j < 64; j++) s += g_meanpart[(base64 + j) * DD + d];
    out[i] = s * (1.0f / (float)TT);
}

// ---------------- fallback k3a: tanh + softmax over T -> weights --------------
__global__ void k3a_weights() {
    if (g_need_full == 0) return;
    __shared__ float red[256];
    int tid = threadIdx.x;
    int which = blockIdx.x >> 4;
    int b = blockIdx.x & 15;
    const unsigned* src = (which ? g_cmax : g_rmax) + b * TT;
    float* dst = g_wts + (size_t)(which * BB + b) * TT;

    float tv[8];
    #pragma unroll
    for (int i = 0; i < 8; i++) tv[i] = tanhf(decf(src[i * 256 + tid]));

    float lm = tv[0];
    #pragma unroll
    for (int i = 1; i < 8; i++) lm = fmaxf(lm, tv[i]);
    red[tid] = lm;
    __syncthreads();
    for (int s = 128; s > 0; s >>= 1) {
        if (tid < s) red[tid] = fmaxf(red[tid], red[tid + s]);
        __syncthreads();
    }
    float mx = red[0];
    __syncthreads();

    float ls = 0.0f;
    #pragma unroll
    for (int i = 0; i < 8; i++) ls += expf(tv[i] - mx);
    red[tid] = ls;
    __syncthreads();
    for (int s = 128; s > 0; s >>= 1) {
        if (tid < s) red[tid] += red[tid + s];
        __syncthreads();
    }
    float inv = 1.0f / red[0];

    #pragma unroll
    for (int i = 0; i < 8; i++) dst[i * 256 + tid] = expf(tv[i] - mx) * inv;
}

// ---------------- fallback k3b: weighted pooling partials ----------------------
__global__ void k3b_pool(const float* __restrict__ q, const float* __restrict__ a) {
    if (g_need_full == 0) return;
    __shared__ float ws[256];
    int tid = threadIdx.x;
    int slice = blockIdx.x & 7;
    int b     = (blockIdx.x >> 3) & 15;
    int which = blockIdx.x >> 7;

    ws[tid] = g_wts[(size_t)(which * BB + b) * TT + slice * 256 + tid];
    __syncthreads();

    const float* src = which ? a : q;
    const float* base = src + ((size_t)b * TT + (size_t)slice * 256) * DD + tid;
    float acc = 0.0f;
    #pragma unroll 8
    for (int t = 0; t < 256; t++) acc += ws[t] * base[(size_t)t * DD];
    g_part[(size_t)blockIdx.x * 256 + tid] = acc;
}

// ---------------- fallback k3c: reduce partials -> output ----------------------
__global__ void k3c_reduce(float* __restrict__ out) {
    if (g_need_full == 0) return;
    int i = blockIdx.x * 256 + threadIdx.x;
    int which = i >> 12;
    int b = (i >> 8) & 15;
    int d = i & 255;
    size_t pb = ((size_t)(which * BB + b) * 8) * 256 + d;
    float s = 0.0f;
    #pragma unroll
    for (int k = 0; k < 8; k++) s += g_part[pb + (size_t)k * 256];
    out[i] = s;
}

// ---------------- launch ------------------------------------------------------
extern "C" void kernel_launch(void* const* d_in, const int* in_sizes, int n_in,
                              void* d_out, int out_size) {
    int ui = 2;
    for (int i = 0; i < n_in; i++)
        if (in_sizes[i] == DD * DD) ui = i;
    const float* ptrs[3];
    int k = 0;
    for (int i = 0; i < n_in && k < 3; i++)
        if (i != ui) ptrs[k++] = (const float*)d_in[i];
    const float* q = ptrs[0];
    const float* a = ptrs[1];
    const float* U = (const float*)d_in[ui];
    float* out = (float*)d_out;

    // One-time setup (runs on the uncaptured correctness call; capture call
    // only performs launches + event record/wait, which are graph-capturable).
    static int init_done = 0;
    static cudaStream_t s1;
    static cudaEvent_t ev_fork, ev_a_done, ev_k1a, ev_col;
    if (!init_done) {
        cudaFuncSetAttribute(k1_qU, cudaFuncAttributeMaxDynamicSharedMemorySize, GEMM_SMEM);
        cudaFuncSetAttribute(k2_gemm_max, cudaFuncAttributeMaxDynamicSharedMemorySize, GEMM_SMEM);
        cudaStreamCreateWithFlags(&s1, cudaStreamNonBlocking);
        cudaEventCreateWithFlags(&ev_fork,   cudaEventDisableTiming);
        cudaEventCreateWithFlags(&ev_a_done, cudaEventDisableTiming);
        cudaEventCreateWithFlags(&ev_k1a,    cudaEventDisableTiming);
        cudaEventCreateWithFlags(&ev_col,    cudaEventDisableTiming);
        init_done = 1;
    }

    // fork: a-convert on s1, everything else on stream 0
    cudaEventRecord(ev_fork, 0);
    cudaStreamWaitEvent(s1, ev_fork, 0);

    // s0: q convert (+U transpose, zero maxes); s1: a convert
    k0_convert<<<324, 256>>>(q, U, g_qb, 0, 1);
    k0_convert<<<256, 256, 0, s1>>>(a, U, g_ab, 256, 0);
    cudaEventRecord(ev_a_done, s1);

    // s0: qU rows {0,1} per batch first (all col-cert needs), then the rest
    k1_qU<<<dim3(2, 32), 256, GEMM_SMEM>>>(0);
    cudaEventRecord(ev_k1a, 0);
    k1_qU<<<dim3(2, 224), 256, GEMM_SMEM>>>(1);

    // s1: col-cert (needs a-convert [already ordered on s1] + k1a)
    cudaStreamWaitEvent(s1, ev_k1a, 0);
    k2_gemm_max<<<dim3(14, 2, 16), 256, GEMM_SMEM, s1>>>(2, 0, 0);
    cudaEventRecord(ev_col, s1);

    // s0: row-cert (needs all qU + a-convert)
    cudaStreamWaitEvent(0, ev_a_done, 0);
    k2_gemm_max<<<dim3(2, 16, 16), 256, GEMM_SMEM>>>(0, 0, 0);

    // join col-cert, then check + certified output
    cudaStreamWaitEvent(0, ev_col, 0);
    k_check<<<256, 256>>>();
    k_out_mean<<<32, 256>>>(out);

    // fallback (self-disabled when certified): only tiles cert didn't cover
    k2_gemm_max<<<dim3(14, 14, 16), 256, GEMM_SMEM>>>(2, 2, 1);
    k3a_weights<<<32, 256>>>();
    k3b_pool<<<256, 256>>>(q, a);
    k3c_reduce<<<32, 256>>>(out);
    (void)out_size;
}

// round 6
// speedup vs baseline: 4.0677x; 4.0677x over previous
#include <cuda_runtime.h>
#include <cuda_bf16.h>
#include <stdint.h>
#include <math.h>

#define BB 16
#define TT 2048
#define DD 256

// Certification threshold: computed (bf16-mma) lower bound on a row/col max.
// tanh saturates to exactly 1.0f for x >= ~9.0; bf16 pipeline error << 0.6,
// so a computed bound >= 9.6 certifies saturation of that row/col max.
#define CERT_THRESH 9.6f

// ---------------- scratch (static __device__ arrays; no runtime allocation) ----
__device__ __nv_bfloat16 g_qb[BB*TT*DD];    // q in bf16
__device__ __nv_bfloat16 g_ab[BB*TT*DD];    // a in bf16
__device__ __nv_bfloat16 g_Ut[DD*DD];       // U^T in bf16 (Ut[e][d] = U[d][e])
__device__ __nv_bfloat16 g_Ub[DD*DD];       // U in bf16 (row-major, as reference)
__device__ __nv_bfloat16 g_qU[BB*TT*DD];    // qU in bf16 (rows 0..255/batch + gated rest)
__device__ __nv_bfloat16 g_Wt[BB*256*DD];   // Wt[b][j][d] = sum_e a[b,j,e]*U[d,e]
__device__ unsigned      g_rmax[BB*TT];     // encoded float max per q-row
__device__ unsigned      g_cmax[BB*TT];     // encoded float max per a-col
__device__ float         g_wts[2*BB*TT];    // softmax weights (fallback)
__device__ float         g_part[2*BB*8*DD]; // pooling partials (fallback)
__device__ float         g_meanpart[4096*DD]; // per-(block,rowgroup) mean partials
__device__ int           g_need_full;       // 0 = certified (means exact)

// ---------------- helpers ----------------
__device__ __forceinline__ uint32_t smem_u32(const void* p) {
    uint32_t r;
    asm("{ .reg .u64 t; cvta.to.shared.u64 t, %1; cvt.u32.u64 %0, t; }"
        : "=r"(r) : "l"(p));
    return r;
}

__device__ __forceinline__ void cpasync16(uint32_t s, const void* g) {
    asm volatile("cp.async.cg.shared.global [%0], [%1], 16;" :: "r"(s), "l"(g) : "memory");
}
#define CP_COMMIT() asm volatile("cp.async.commit_group;" ::: "memory")
#define CP_WAIT0()  asm volatile("cp.async.wait_group 0;" ::: "memory")

__device__ __forceinline__ void ldmx4(uint32_t addr, uint32_t& r0, uint32_t& r1,
                                      uint32_t& r2, uint32_t& r3) {
    asm volatile("ldmatrix.sync.aligned.m8n8.x4.shared.b16 {%0,%1,%2,%3}, [%4];"
                 : "=r"(r0), "=r"(r1), "=r"(r2), "=r"(r3) : "r"(addr));
}

__device__ __forceinline__ void mma16816(float* c, uint32_t a0, uint32_t a1,
                                         uint32_t a2, uint32_t a3,
                                         uint32_t b0, uint32_t b1) {
    asm volatile(
        "mma.sync.aligned.m16n8k16.row.col.f32.bf16.bf16.f32 "
        "{%0,%1,%2,%3}, {%4,%5,%6,%7}, {%8,%9}, {%0,%1,%2,%3};"
        : "+f"(c[0]), "+f"(c[1]), "+f"(c[2]), "+f"(c[3])
        : "r"(a0), "r"(a1), "r"(a2), "r"(a3), "r"(b0), "r"(b1));
}

// order-preserving float <-> unsigned encoding (atomicMax(unsigned) == float max)
__device__ __forceinline__ unsigned encf(float f) {
    unsigned u = __float_as_uint(f);
    return (u & 0x80000000u) ? ~u : (u | 0x80000000u);
}
__device__ __forceinline__ float decf(unsigned e) {
    unsigned u = (e & 0x80000000u) ? (e & 0x7FFFFFFFu) : ~e;
    return __uint_as_float(u);
}

// ---------------- GEMM core: C[128x128] = A[128x256] * B[128x256]^T -----------
#define GEMM_SMEM 65536

__device__ __forceinline__ void load_chunk(uint32_t smb, int buf,
                                           const __nv_bfloat16* __restrict__ A,
                                           const __nv_bfloat16* __restrict__ Bm,
                                           int ck, int tid) {
    const __nv_bfloat16* Ac = A + ck * 64;
    const __nv_bfloat16* Bc = Bm + ck * 64;
    #pragma unroll
    for (int i = 0; i < 4; i++) {
        int v = tid + i * 256;
        int row = v >> 3, kv = v & 7;
        uint32_t o = (uint32_t)row * 128u + (uint32_t)kv * 16u;
        o ^= (o >> 3) & 0x70u;
        const size_t goff = (size_t)row * DD + (size_t)kv * 8;
        cpasync16(smb + buf * 16384 + o, Ac + goff);
        cpasync16(smb + 32768 + buf * 16384 + o, Bc + goff);
    }
}

// Single-sync double-buffered pipeline:
//   wait(chunk ck) -> syncthreads -> prefetch ck+1 -> compute ck
__device__ __forceinline__ void gemm_mainloop(uint32_t smb, const __nv_bfloat16* A,
                                              const __nv_bfloat16* Bm, int tid,
                                              float acc[4][4][4]) {
    const int lid = tid & 31, w = tid >> 5;
    const int wm = (w >> 2) * 64, wn = (w & 3) * 32;
    const int lrow = lid & 15;
    const uint32_t khalf = (uint32_t)(lid >> 4) * 16u;

    load_chunk(smb, 0, A, Bm, 0, tid);
    CP_COMMIT();

    #pragma unroll
    for (int ck = 0; ck < 4; ck++) {
        CP_WAIT0();
        __syncthreads();
        if (ck + 1 < 4) {
            load_chunk(smb, (ck + 1) & 1, A, Bm, ck + 1, tid);
            CP_COMMIT();
        }

        const uint32_t abase = smb + (ck & 1) * 16384;
        const uint32_t bbase = smb + 32768 + (ck & 1) * 16384;

        #pragma unroll
        for (int kk = 0; kk < 4; kk++) {
            const uint32_t koff = (uint32_t)kk * 32u + khalf;
            uint32_t a[4][4];
            #pragma unroll
            for (int mt = 0; mt < 4; mt++) {
                uint32_t o = (uint32_t)(wm + mt * 16 + lrow) * 128u + koff;
                o ^= (o >> 3) & 0x70u;
                ldmx4(abase + o, a[mt][0], a[mt][1], a[mt][2], a[mt][3]);
            }
            uint32_t b[4][2];
            #pragma unroll
            for (int np = 0; np < 2; np++) {
                uint32_t o = (uint32_t)(wn + np * 16 + lrow) * 128u + koff;
                o ^= (o >> 3) & 0x70u;
                uint32_t r0, r1, r2, r3;
                ldmx4(bbase + o, r0, r1, r2, r3);
                b[np * 2 + 0][0] = r0; b[np * 2 + 0][1] = r2;
                b[np * 2 + 1][0] = r1; b[np * 2 + 1][1] = r3;
            }
            #pragma unroll
            for (int mt = 0; mt < 4; mt++)
                #pragma unroll
                for (int nt = 0; nt < 4; nt++)
                    mma16816(acc[mt][nt], a[mt][0], a[mt][1], a[mt][2], a[mt][3],
                             b[nt][0], b[nt][1]);
        }
    }
}

// shared epilogues ------------------------------------------------------------
__device__ __forceinline__ void epi_store_bf16(const float acc[4][4][4], int tid,
                                               __nv_bfloat16* dstbase, int rowOff,
                                               int colOff, int rowStride) {
    const int lid = tid & 31, w = tid >> 5;
    const int wm = (w >> 2) * 64, wn = (w & 3) * 32;
    const int g = lid >> 2, tg = lid & 3;
    #pragma unroll
    for (int mt = 0; mt < 4; mt++) {
        int row0 = rowOff + wm + mt * 16 + g;
        #pragma unroll
        for (int nt = 0; nt < 4; nt++) {
            int col = colOff + wn + nt * 8 + 2 * tg;
            __nv_bfloat162 p0 = __floats2bfloat162_rn(acc[mt][nt][0], acc[mt][nt][1]);
            __nv_bfloat162 p1 = __floats2bfloat162_rn(acc[mt][nt][2], acc[mt][nt][3]);
            *reinterpret_cast<unsigned*>(dstbase + (size_t)row0 * rowStride + col) =
                *reinterpret_cast<unsigned*>(&p0);
            *reinterpret_cast<unsigned*>(dstbase + (size_t)(row0 + 8) * rowStride + col) =
                *reinterpret_cast<unsigned*>(&p1);
        }
    }
}

__device__ __forceinline__ void epi_max(const float acc[4][4][4], int tid,
                                        int rowBase, int colBase) {
    const int lid = tid & 31, w = tid >> 5;
    const int wm = (w >> 2) * 64, wn = (w & 3) * 32;
    const int g = lid >> 2, tg = lid & 3;
    const int rb = rowBase + wm;
    const int cb = colBase + wn;

    #pragma unroll
    for (int mt = 0; mt < 4; mt++) {
        float r0 = -3.0e38f, r1 = -3.0e38f;
        #pragma unroll
        for (int nt = 0; nt < 4; nt++) {
            r0 = fmaxf(r0, fmaxf(acc[mt][nt][0], acc[mt][nt][1]));
            r1 = fmaxf(r1, fmaxf(acc[mt][nt][2], acc[mt][nt][3]));
        }
        r0 = fmaxf(r0, __shfl_xor_sync(0xffffffffu, r0, 1));
        r0 = fmaxf(r0, __shfl_xor_sync(0xffffffffu, r0, 2));
        r1 = fmaxf(r1, __shfl_xor_sync(0xffffffffu, r1, 1));
        r1 = fmaxf(r1, __shfl_xor_sync(0xffffffffu, r1, 2));
        if (tg == 0) {
            atomicMax(&g_rmax[rb + mt * 16 + g], encf(r0));
            atomicMax(&g_rmax[rb + mt * 16 + g + 8], encf(r1));
        }
    }
    #pragma unroll
    for (int nt = 0; nt < 4; nt++) {
        float c0 = -3.0e38f, c1 = -3.0e38f;
        #pragma unroll
        for (int mt = 0; mt < 4; mt++) {
            c0 = fmaxf(c0, fmaxf(acc[mt][nt][0], acc[mt][nt][2]));
            c1 = fmaxf(c1, fmaxf(acc[mt][nt][1], acc[mt][nt][3]));
        }
        #pragma unroll
        for (int s = 4; s < 32; s <<= 1) {
            c0 = fmaxf(c0, __shfl_xor_sync(0xffffffffu, c0, s));
            c1 = fmaxf(c1, __shfl_xor_sync(0xffffffffu, c1, s));
        }
        if (g == 0) {
            atomicMax(&g_cmax[cb + nt * 8 + 2 * tg], encf(c0));
            atomicMax(&g_cmax[cb + nt * 8 + 2 * tg + 1], encf(c1));
        }
    }
}

#define ACC_DECL_ZERO(acc) \
    float acc[4][4][4]; \
    _Pragma("unroll") for (int _i = 0; _i < 4; _i++) \
    _Pragma("unroll") for (int _j = 0; _j < 4; _j++) \
    _Pragma("unroll") for (int _r = 0; _r < 4; _r++) acc[_i][_j][_r] = 0.0f;

// ---------------- k0: convert fp32->bf16 + mean partials + aux ---------------
// bx < 1024: convert 64-row chunks (q: bx<512, a: 512..1023).
// bx in [1024,1088): 64 zero blocks; [1088,1096): 8 U blocks (4 Ut + 4 Ub).
__global__ void __launch_bounds__(256) k0_convert(const float* __restrict__ q,
                                                  const float* __restrict__ a,
                                                  const float* __restrict__ U) {
    int bx = blockIdx.x;
    int tid = threadIdx.x;

    if (bx >= 1024) {
        int bz = bx - 1024;
        if (bz < 64) {
            int i0 = (bz * 256 + tid) * 2;
            g_rmax[i0] = 0u; g_rmax[i0 + 1] = 0u;
            g_cmax[i0] = 0u; g_cmax[i0 + 1] = 0u;
            if (bz == 0 && tid == 0) g_need_full = 0;
        } else if (bz < 68) {
            int blk = bz - 64;   // Ut
            #pragma unroll 4
            for (int it = 0; it < 64; it++) {
                int i = blk * 16384 + it * 256 + tid;
                int d = i >> 8, e = i & 255;
                g_Ut[e * DD + d] = __float2bfloat16(U[i]);
            }
        } else {
            int blk = bz - 68;   // Ub (straight)
            #pragma unroll 4
            for (int it = 0; it < 64; it++) {
                int i = blk * 16384 + it * 256 + tid;
                g_Ub[i] = __float2bfloat16(U[i]);
            }
        }
        return;
    }

    int tensor = bx >> 9;
    int local = bx & 511;
    int b = local >> 5;
    int chunk = local & 31;   // 64-row chunk
    const float4* src = (const float4*)((tensor ? a : q) +
                        ((size_t)b * TT + (size_t)chunk * 64) * DD);
    uint2* dst = (uint2*)((tensor ? g_ab : g_qb) +
                 ((size_t)b * TT + (size_t)chunk * 64) * DD);

    const int dvec = tid & 63;          // float4 index within row
    const int rg = tid >> 6;            // row group 0..3
    float4 s = make_float4(0.f, 0.f, 0.f, 0.f);
    #pragma unroll 4
    for (int it = 0; it < 16; it++) {
        int row = it * 4 + rg;
        float4 v = src[(size_t)row * 64 + dvec];
        s.x += v.x; s.y += v.y; s.z += v.z; s.w += v.w;
        __nv_bfloat162 lo = __floats2bfloat162_rn(v.x, v.y);
        __nv_bfloat162 hi = __floats2bfloat162_rn(v.z, v.w);
        uint2 o;
        o.x = *reinterpret_cast<unsigned*>(&lo);
        o.y = *reinterpret_cast<unsigned*>(&hi);
        dst[(size_t)row * 64 + dvec] = o;
    }
    float4* mp = (float4*)&g_meanpart[((size_t)bx * 4 + rg) * DD];
    mp[dvec] = s;
}

// ---------------- kW: Wt[b] = a_sel @ U^T  (a rows 0..255 per batch) ----------
__global__ void __launch_bounds__(256, 2) kW() {
    extern __shared__ char sm[];
    uint32_t smb = smem_u32(sm);
    int tid = threadIdx.x;
    int tileN = blockIdx.x;   // d block 0..1
    int tileM = blockIdx.y;   // j block 0..1
    int b = blockIdx.z;

    ACC_DECL_ZERO(acc);
    const __nv_bfloat16* A = g_ab + ((size_t)b * TT + (size_t)tileM * 128) * DD;
    const __nv_bfloat16* Bm = g_Ub + (size_t)tileN * 128 * DD;
    gemm_mainloop(smb, A, Bm, tid, acc);
    epi_store_bf16(acc, tid, g_Wt + (size_t)b * 256 * DD, tileM * 128, tileN * 128, DD);
}

// ---------------- kG_sample: G[:, 0:256] = q @ Wt^T, fused max ----------------
// Row maxes: 256-col sample for every q-row. Col maxes: EXACT for cols 0..255.
__global__ void __launch_bounds__(256, 2) kG_sample() {
    extern __shared__ char sm[];
    uint32_t smb = smem_u32(sm);
    int tid = threadIdx.x;
    int tileN = blockIdx.x;   // j block 0..1
    int y = blockIdx.y;       // 0..255 (global q row-block)
    int b = y >> 4;

    ACC_DECL_ZERO(acc);
    const __nv_bfloat16* A = g_qb + (size_t)y * 128 * DD;
    const __nv_bfloat16* Bm = g_Wt + (size_t)b * 256 * DD + (size_t)tileN * 128 * DD;
    gemm_mainloop(smb, A, Bm, tid, acc);
    epi_max(acc, tid, y * 128, b * TT + tileN * 128);
}

// ---------------- k1: qU tiles (part 0: rows{0,1}/batch; part 1: rest, gated) -
__global__ void __launch_bounds__(256, 2) k1_qU(int part, int gated) {
    if (gated && g_need_full == 0) return;
    extern __shared__ char sm[];
    uint32_t smb = smem_u32(sm);
    int tid = threadIdx.x;
    int tileN = blockIdx.x;   // 0..1
    int y = blockIdx.y;
    int tileM = part ? ((y / 14) * 16 + 2 + (y % 14))
                     : ((y >> 1) * 16 + (y & 1));

    ACC_DECL_ZERO(acc);
    const __nv_bfloat16* A = g_qb + (size_t)tileM * 128 * DD;
    const __nv_bfloat16* Bm = g_Ut + (size_t)tileN * 128 * DD;
    gemm_mainloop(smb, A, Bm, tid, acc);
    epi_store_bf16(acc, tid, g_qU, tileM * 128, tileN * 128, DD);
}

// ---------------- k2: G tile GEMM (qU path) with fused row/col max ------------
__global__ void __launch_bounds__(256, 2) k2_gemm_max(int njoff, int mioff, int gated) {
    if (gated && g_need_full == 0) return;
    extern __shared__ char sm[];
    uint32_t smb = smem_u32(sm);
    int tid = threadIdx.x;
    int nj = blockIdx.x + njoff;
    int mi = blockIdx.y + mioff;
    int b  = blockIdx.z;

    ACC_DECL_ZERO(acc);
    const __nv_bfloat16* A = g_qU + ((size_t)b * TT + (size_t)mi * 128) * DD;
    const __nv_bfloat16* Bm = g_ab + ((size_t)b * TT + (size_t)nj * 128) * DD;
    gemm_mainloop(smb, A, Bm, tid, acc);
    epi_max(acc, tid, b * TT + mi * 128, b * TT + nj * 128);
}

// ---------------- k_check: certify saturation of every row/col max ------------
__global__ void k_check() {
    int i = blockIdx.x * 256 + threadIdx.x;   // 0..65535
    unsigned e = (i < BB * TT) ? g_rmax[i] : g_cmax[i - BB * TT];
    if (decf(e) < CERT_THRESH) atomicOr(&g_need_full, 1);
}

// ---------------- k_out: certified path -> means ------------------------------
__global__ void k_out_mean(float* __restrict__ out) {
    if (g_need_full) return;
    int i = blockIdx.x * 256 + threadIdx.x;   // 0..8191
    int which = i >> 12;
    int b = (i >> 8) & 15;
    int d = i & 255;
    size_t base = (size_t)(which * 512 + b * 32) * 4;
    float s = 0.0f;
    #pragma unroll 8
    for (int j = 0; j < 128; j++) s += g_meanpart[(base + j) * DD + d];
    out[i] = s * (1.0f / (float)TT);
}

// ---------------- fallback k3a: tanh + softmax over T -> weights --------------
__global__ void k3a_weights() {
    if (g_need_full == 0) return;
    __shared__ float red[256];
    int tid = threadIdx.x;
    int which = blockIdx.x >> 4;
    int b = blockIdx.x & 15;
    const unsigned* src = (which ? g_cmax : g_rmax) + b * TT;
    float* dst = g_wts + (size_t)(which * BB + b) * TT;

    float tv[8];
    #pragma unroll
    for (int i = 0; i < 8; i++) tv[i] = tanhf(decf(src[i * 256 + tid]));

    float lm = tv[0];
    #pragma unroll
    for (int i = 1; i < 8; i++) lm = fmaxf(lm, tv[i]);
    red[tid] = lm;
    __syncthreads();
    for (int s = 128; s > 0; s >>= 1) {
        if (tid < s) red[tid] = fmaxf(red[tid], red[tid + s]);
        __syncthreads();
    }
    float mx = red[0];
    __syncthreads();

    float ls = 0.0f;
    #pragma unroll
    for (int i = 0; i < 8; i++) ls += expf(tv[i] - mx);
    red[tid] = ls;
    __syncthreads();
    for (int s = 128; s > 0; s >>= 1) {
        if (tid < s) red[tid] += red[tid + s];
        __syncthreads();
    }
    float inv = 1.0f / red[0];

    #pragma unroll
    for (int i = 0; i < 8; i++) dst[i * 256 + tid] = expf(tv[i] - mx) * inv;
}

// ---------------- fallback k3b: weighted pooling partials ----------------------
__global__ void k3b_pool(const float* __restrict__ q, const float* __restrict__ a) {
    if (g_need_full == 0) return;
    __shared__ float ws[256];
    int tid = threadIdx.x;
    int slice = blockIdx.x & 7;
    int b     = (blockIdx.x >> 3) & 15;
    int which = blockIdx.x >> 7;

    ws[tid] = g_wts[(size_t)(which * BB + b) * TT + slice * 256 + tid];
    __syncthreads();

    const float* src = which ? a : q;
    const float* base = src + ((size_t)b * TT + (size_t)slice * 256) * DD + tid;
    float acc = 0.0f;
    #pragma unroll 8
    for (int t = 0; t < 256; t++) acc += ws[t] * base[(size_t)t * DD];
    g_part[(size_t)blockIdx.x * 256 + tid] = acc;
}

// ---------------- fallback k3c: reduce partials -> output ----------------------
__global__ void k3c_reduce(float* __restrict__ out) {
    if (g_need_full == 0) return;
    int i = blockIdx.x * 256 + threadIdx.x;
    int which = i >> 12;
    int b = (i >> 8) & 15;
    int d = i & 255;
    size_t pb = ((size_t)(which * BB + b) * 8) * 256 + d;
    float s = 0.0f;
    #pragma unroll
    for (int k = 0; k < 8; k++) s += g_part[pb + (size_t)k * 256];
    out[i] = s;
}

// ---------------- launch ------------------------------------------------------
extern "C" void kernel_launch(void* const* d_in, const int* in_sizes, int n_in,
                              void* d_out, int out_size) {
    int ui = 2;
    for (int i = 0; i < n_in; i++)
        if (in_sizes[i] == DD * DD) ui = i;
    const float* ptrs[3];
    int k = 0;
    for (int i = 0; i < n_in && k < 3; i++)
        if (i != ui) ptrs[k++] = (const float*)d_in[i];
    const float* q = ptrs[0];
    const float* a = ptrs[1];
    const float* U = (const float*)d_in[ui];
    float* out = (float*)d_out;

    static int init_done = 0;
    if (!init_done) {
        cudaFuncSetAttribute(kW,         cudaFuncAttributeMaxDynamicSharedMemorySize, GEMM_SMEM);
        cudaFuncSetAttribute(kG_sample,  cudaFuncAttributeMaxDynamicSharedMemorySize, GEMM_SMEM);
        cudaFuncSetAttribute(k1_qU,      cudaFuncAttributeMaxDynamicSharedMemorySize, GEMM_SMEM);
        cudaFuncSetAttribute(k2_gemm_max,cudaFuncAttributeMaxDynamicSharedMemorySize, GEMM_SMEM);
        init_done = 1;
    }

    // converts + mean partials + U^T/U + zero maxes (single kernel)
    k0_convert<<<1096, 256>>>(q, a, U);
    // Wt = a_sel @ U^T (64 units)
    kW<<<dim3(2, 2, 16), 256, GEMM_SMEM>>>();
    // qU rows {0,1} per batch (64 units) — feeds col-cert
    k1_qU<<<dim3(2, 32), 256, GEMM_SMEM>>>(0, 0);
    // G[:, 0:256] via W-path: row samples for all rows + exact col maxes 0..255
    kG_sample<<<dim3(2, 256), 256, GEMM_SMEM>>>();
    // col-cert: cols 256..2047 sampled over rows 0..255 (448 units)
    k2_gemm_max<<<dim3(14, 2, 16), 256, GEMM_SMEM>>>(2, 0, 0);
    // certify + certified output
    k_check<<<256, 256>>>();
    k_out_mean<<<32, 256>>>(out);
    // fallback (self-disabled when certified): complete qU, remaining tiles, exact pipeline
    k1_qU<<<dim3(2, 224), 256, GEMM_SMEM>>>(1, 1);
    k2_gemm_max<<<dim3(14, 14, 16), 256, GEMM_SMEM>>>(2, 2, 1);
    k3a_weights<<<32, 256>>>();
    k3b_pool<<<256, 256>>>(q, a);
    k3c_reduce<<<32, 256>>>(out);
    (void)out_size;
}